// round 15
// baseline (speedup 1.0000x reference)
#include <cuda_runtime.h>
#include <cuda_fp16.h>
#include <cstdint>

// Problem constants
#define B_SZ   4
#define S_LEN  2048
#define D_MOD  1024
#define F_DIM  4096
#define N_HEAD 16
#define HD     64
#define ROWS   (B_SZ * S_LEN)        // 8192
#define QKV_N  (3 * D_MOD)           // 3072
#define LN_EPS 1e-5f

// ---------------- scratch (device globals; no allocation) ----------------
__device__ __half g_h  [ROWS * D_MOD];
__device__ __half g_qkv[ROWS * QKV_N];
__device__ __half g_ctx[ROWS * D_MOD];
__device__ float  g_x1 [ROWS * D_MOD];
__device__ __half g_mid[ROWS * F_DIM];
__device__ float  g_pool[B_SZ * D_MOD];
__device__ float  g_pp [B_SZ * 32 * D_MOD];
__device__ __half g_wqkv[D_MOD * QKV_N];
__device__ __half g_wo [D_MOD * D_MOD];
__device__ __half g_w1 [D_MOD * F_DIM];
__device__ __half g_w2 [F_DIM * D_MOD];

// ======================= helpers =======================
__device__ __forceinline__ uint32_t smem_u32(const void* p) {
    uint32_t a;
    asm("{ .reg .u64 t; cvta.to.shared.u64 t, %1; cvt.u32.u64 %0, t; }" : "=r"(a) : "l"(p));
    return a;
}
__device__ __forceinline__ void ldm_x4(uint32_t* r, uint32_t addr) {
    asm volatile("ldmatrix.sync.aligned.m8n8.x4.shared.b16 {%0,%1,%2,%3}, [%4];"
        : "=r"(r[0]), "=r"(r[1]), "=r"(r[2]), "=r"(r[3]) : "r"(addr));
}
__device__ __forceinline__ void ldm_x4t(uint32_t* r, uint32_t addr) {
    asm volatile("ldmatrix.sync.aligned.m8n8.x4.trans.shared.b16 {%0,%1,%2,%3}, [%4];"
        : "=r"(r[0]), "=r"(r[1]), "=r"(r[2]), "=r"(r[3]) : "r"(addr));
}
__device__ __forceinline__ void mma_f16(float* c, const uint32_t* a, const uint32_t* b) {
    asm volatile(
        "mma.sync.aligned.m16n8k16.row.col.f32.f16.f16.f32 "
        "{%0,%1,%2,%3}, {%4,%5,%6,%7}, {%8,%9}, {%0,%1,%2,%3};"
        : "+f"(c[0]), "+f"(c[1]), "+f"(c[2]), "+f"(c[3])
        : "r"(a[0]), "r"(a[1]), "r"(a[2]), "r"(a[3]), "r"(b[0]), "r"(b[1]));
}
__device__ __forceinline__ void cp16(uint32_t dst, const void* src) {
    asm volatile("cp.async.cg.shared.global [%0], [%1], 16;" :: "r"(dst), "l"(src));
}
__device__ __forceinline__ void cp_commit() { asm volatile("cp.async.commit_group;" ::: "memory"); }
template <int N>
__device__ __forceinline__ void cp_waitN() {
    asm volatile("cp.async.wait_group %0;" :: "n"(N) : "memory");
}
__device__ __forceinline__ uint32_t pack_h2(__half a, __half b) {
    __half2 v; v.x = a; v.y = b;
    return *reinterpret_cast<uint32_t*>(&v);
}

// ======================= pipelined HMMA GEMM (fp16, 128x128, BK=32, 4-stage, 1 sync/chunk) =======================
#define TCBM 128
#define TCBN 128
#define TCBK 32
#define A_PITCH 80
#define B_PITCH 272
#define SM_A    0
#define SM_B    10240
#define SM_BUF  18944
#define N_STAGE 4
#define SM_TOT  (N_STAGE * SM_BUF)     // 75776

// qcols: SPLIT-output columns < qcols are scaled by qscale (Q pre-scaling for attention)
template <bool RELU, bool SPLIT>
__global__ __launch_bounds__(256, 2) void hmma_gemm(
    const __half* __restrict__ A, const __half* __restrict__ Bm,
    const float* __restrict__ bias, const float* __restrict__ resid,
    float* __restrict__ C, __half* __restrict__ Ch,
    int M, int N, int K, int qcols, float qscale)
{
    extern __shared__ char smem[];
    const uint32_t sb = smem_u32(smem);

    const int tid = threadIdx.x;
    const int wid = tid >> 5, lane = tid & 31;
    const int warp_m = wid & 1;
    const int warp_n = wid >> 1;
    const int m0 = blockIdx.y * TCBM, n0 = blockIdx.x * TCBN;

    const int aR0 = tid >> 1, aC0 = (tid & 1) << 1;
    const int bR0 = tid >> 3, bC0 = (tid & 7) << 1;

    float c[4][4][4];
    #pragma unroll
    for (int i = 0; i < 4; ++i)
        #pragma unroll
        for (int j = 0; j < 4; ++j)
            #pragma unroll
            for (int f = 0; f < 4; ++f) c[i][j][f] = 0.f;

    const uint32_t a_row = (uint32_t)(warp_m * 64 + (lane & 15));
    const uint32_t a_cb  = (uint32_t)((lane >> 4) << 4);
    const uint32_t b_row = (uint32_t)(lane & 15);
    const uint32_t b_cb  = (uint32_t)(warp_n * 64 + ((lane >> 4) << 4));

    const int NC = K / TCBK;

    auto issue = [&](int ch, int st) {
        const uint32_t bb = sb + st * SM_BUF;
        const int k0 = ch * TCBK;
        #pragma unroll
        for (int i = 0; i < 2; ++i) {
            int ck = aC0 + i;
            cp16(bb + SM_A + aR0 * A_PITCH + ck * 16,
                 A + (size_t)(m0 + aR0) * K + k0 + ck * 8);
        }
        #pragma unroll
        for (int i = 0; i < 2; ++i) {
            int ck = bC0 + i;
            cp16(bb + SM_B + bR0 * B_PITCH + ck * 16,
                 Bm + (size_t)(k0 + bR0) * N + n0 + ck * 8);
        }
        cp_commit();
    };

    issue(0, 0); issue(1, 1); issue(2, 2);

    int st_c = 0, st_i = 3;
    for (int ch = 0; ch < NC; ++ch) {
        cp_waitN<2>();                   // group ch complete (ch+1, ch+2 may remain in flight)
        __syncthreads();                 // all threads see stage st_c data; stage st_i compute done
        if (ch + 3 < NC) issue(ch + 3, st_i);
        else             cp_commit();    // keep group counts aligned

        const uint32_t bb = sb + st_c * SM_BUF;
        #pragma unroll
        for (int ks = 0; ks < 2; ++ks) {
            uint32_t bh[4][2];
            uint32_t b_addr = bb + SM_B + (b_row + ks * 16) * B_PITCH + b_cb;
            #pragma unroll
            for (int nt2 = 0; nt2 < 2; ++nt2) {
                uint32_t t4[4];
                ldm_x4t(t4, b_addr + nt2 * 32);
                bh[nt2 * 2][0] = t4[0]; bh[nt2 * 2][1] = t4[1];
                bh[nt2 * 2 + 1][0] = t4[2]; bh[nt2 * 2 + 1][1] = t4[3];
            }
            uint32_t a_addr = bb + SM_A + a_row * A_PITCH + a_cb + ks * 32;
            #pragma unroll
            for (int mt = 0; mt < 4; ++mt) {
                uint32_t ah[4];
                ldm_x4(ah, a_addr + mt * 16 * A_PITCH);
                #pragma unroll
                for (int nt = 0; nt < 4; ++nt)
                    mma_f16(c[mt][nt], ah, bh[nt]);
            }
        }
        st_c = (st_c == N_STAGE - 1) ? 0 : st_c + 1;
        st_i = (st_i == N_STAGE - 1) ? 0 : st_i + 1;
    }

    const int er = lane >> 2, ec = (lane & 3) * 2;
    #pragma unroll
    for (int mt = 0; mt < 4; ++mt) {
        #pragma unroll
        for (int nt = 0; nt < 4; ++nt) {
            int gr = m0 + warp_m * 64 + mt * 16 + er;
            int gc = n0 + warp_n * 32 + nt * 8 + ec;
            #pragma unroll
            for (int half = 0; half < 2; ++half) {
                int row = gr + half * 8;
                float v0 = c[mt][nt][half * 2 + 0];
                float v1 = c[mt][nt][half * 2 + 1];
                if (bias) { v0 += bias[gc]; v1 += bias[gc + 1]; }
                if (resid) {
                    float2 r2 = *(const float2*)(resid + (size_t)row * N + gc);
                    v0 += r2.x; v1 += r2.y;
                }
                if (RELU) { v0 = fmaxf(v0, 0.f); v1 = fmaxf(v1, 0.f); }
                if (SPLIT) {
                    if (gc < qcols) { v0 *= qscale; v1 *= qscale; }
                    *(uint32_t*)(Ch + (size_t)row * N + gc) =
                        pack_h2(__float2half(v0), __float2half(v1));
                } else {
                    *(float2*)(C + (size_t)row * N + gc) = make_float2(v0, v1);
                }
            }
        }
    }
}

// ---------------- fused weight convert: all 6 matrices in one launch ----------------
__global__ void conv_all(const float* __restrict__ Wq, const float* __restrict__ Wk,
                         const float* __restrict__ Wv, const float* __restrict__ Wo,
                         const float* __restrict__ W1, const float* __restrict__ W2,
                         __half* __restrict__ wqkv, __half* __restrict__ wo,
                         __half* __restrict__ w1, __half* __restrict__ w2) {
    const int U = D_MOD * D_MOD / 4;
    int idx = blockIdx.x * blockDim.x + threadIdx.x;
    const float* src; __half* dst;
    int cols, dstride, coff;
    if (idx < U)          { src = Wq; dst = wqkv; cols = D_MOD; dstride = QKV_N; coff = 0; }
    else if (idx < 2 * U) { src = Wk; dst = wqkv; cols = D_MOD; dstride = QKV_N; coff = D_MOD;   idx -= U; }
    else if (idx < 3 * U) { src = Wv; dst = wqkv; cols = D_MOD; dstride = QKV_N; coff = 2*D_MOD; idx -= 2*U; }
    else if (idx < 4 * U) { src = Wo; dst = wo;   cols = D_MOD; dstride = D_MOD; coff = 0; idx -= 3*U; }
    else if (idx < 8 * U) { src = W1; dst = w1;   cols = F_DIM; dstride = F_DIM; coff = 0; idx -= 4*U; }
    else                  { src = W2; dst = w2;   cols = D_MOD; dstride = D_MOD; coff = 0; idx -= 8*U; }
    float4 v = *(const float4*)(src + (size_t)idx * 4);
    int e = idx * 4;
    int r = e / cols, cc = e % cols;
    size_t d = (size_t)r * dstride + coff + cc;
    *(uint2*)(dst + d) = make_uint2(pack_h2(__float2half(v.x), __float2half(v.y)),
                                    pack_h2(__float2half(v.z), __float2half(v.w)));
}

// ---------------- block reduction helper ----------------
__device__ __forceinline__ float block_sum_256(float v, float* sred) {
    int lane = threadIdx.x & 31, w = threadIdx.x >> 5;
    #pragma unroll
    for (int o = 16; o; o >>= 1) v += __shfl_xor_sync(0xffffffffu, v, o);
    if (lane == 0) sred[w] = v;
    __syncthreads();
    float r = (threadIdx.x < 8) ? sred[threadIdx.x] : 0.0f;
    if (w == 0) {
        #pragma unroll
        for (int o = 4; o; o >>= 1) r += __shfl_xor_sync(0x000000ffu, r, o);
        if (lane == 0) sred[0] = r;
    }
    __syncthreads();
    float out = sred[0];
    __syncthreads();
    return out;
}

// ---------------- LayerNorm -> fp16 (vectorized) ----------------
__global__ void ln_kernel(const float* __restrict__ x, const float* __restrict__ w,
                          const float* __restrict__ b, __half* __restrict__ oh) {
    __shared__ float sred[8];
    size_t row = blockIdx.x;
    int t = threadIdx.x;
    float4 v = *(const float4*)(x + row * D_MOD + t * 4);
    float s = v.x + v.y + v.z + v.w;
    float mu = block_sum_256(s, sred) * (1.0f / D_MOD);
    float dx = v.x - mu, dy = v.y - mu, dz = v.z - mu, dw = v.w - mu;
    float d2 = dx * dx + dy * dy + dz * dz + dw * dw;
    float var = block_sum_256(d2, sred) * (1.0f / D_MOD);
    float inv = rsqrtf(var + LN_EPS);
    float4 wv = *(const float4*)(w + t * 4);
    float4 bv = *(const float4*)(b + t * 4);
    __half h0 = __float2half(dx * inv * wv.x + bv.x);
    __half h1 = __float2half(dy * inv * wv.y + bv.y);
    __half h2 = __float2half(dz * inv * wv.z + bv.z);
    __half h3 = __float2half(dw * inv * wv.w + bv.w);
    *(uint2*)(oh + row * D_MOD + t * 4) = make_uint2(pack_h2(h0, h1), pack_h2(h2, h3));
}

// ======================= MMA flash attention (causal, fp16, BQ=128, 3-stage KV) =======================
// Q is pre-scaled by log2(e)/sqrt(HD) in the QKV epilogue; softmax in exp2 domain.
#define AQ 128
#define AKT 64
#define APITCH 144
#define ASM_Q 0
#define ASM_KV 18432
#define AKV_STAGE 18432
#define AKV_NS 3
#define ASM_TOT (ASM_KV + AKV_NS * AKV_STAGE)    // 73728

__global__ __launch_bounds__(256, 2) void attn_mma(
    const __half* __restrict__ qkv, __half* __restrict__ ctx)
{
    extern __shared__ char sm[];
    const uint32_t sb = smem_u32(sm);
    const int qb = blockIdx.x;
    const int bh = blockIdx.y;
    const int b = bh >> 4, h = bh & 15;
    const int tid = threadIdx.x, w = tid >> 5, lane = tid & 31;
    const size_t tok0 = (size_t)b * S_LEN;
    const int q0 = qb * AQ;
    const int hcol = h * HD;

    auto issue_kv = [&](int t, int st) {
        const uint32_t kb = sb + ASM_KV + st * AKV_STAGE;
        #pragma unroll
        for (int i = 0; i < 2; ++i) {
            int idx = i * 256 + tid;
            int r = idx >> 3, ck = idx & 7;
            size_t gk = (tok0 + t * AKT + r) * QKV_N + hcol + D_MOD + ck * 8;
            uint32_t off = (uint32_t)(r * APITCH + ck * 16);
            cp16(kb + off, qkv + gk);
            cp16(kb + 9216 + off, qkv + gk + D_MOD);
        }
        cp_commit();
    };

    #pragma unroll
    for (int i = 0; i < 4; ++i) {
        int idx = i * 256 + tid;
        int r = idx >> 3, ck = idx & 7;
        cp16(sb + ASM_Q + r * APITCH + ck * 16,
             qkv + (tok0 + q0 + r) * QKV_N + hcol + ck * 8);
    }
    issue_kv(0, 0);
    issue_kv(1, 1);

    uint32_t qh[4][4];
    float o[8][4];
    #pragma unroll
    for (int nt = 0; nt < 8; ++nt)
        #pragma unroll
        for (int f = 0; f < 4; ++f) o[nt][f] = 0.f;
    float m0 = -1e30f, m1 = -1e30f, l0 = 0.f, l1 = 0.f;

    const uint32_t krow = (uint32_t)((lane & 7) + ((lane >> 4) << 3));
    const uint32_t kcb  = (uint32_t)(((lane >> 3) & 1) << 4);
    const int row_max = q0 + w * 16 + 15;

    const int ntiles = 2 * qb + 2;
    int st_c = 0, st_i = 2;
    for (int t = 0; t < ntiles; ++t) {
        cp_waitN<1>();
        __syncthreads();
        if (t + 2 < ntiles) issue_kv(t + 2, st_i);
        else                cp_commit();

        if (t == 0) {
            uint32_t base = sb + ASM_Q + (uint32_t)(w * 16 + (lane & 15)) * APITCH + ((lane >> 4) << 4);
            #pragma unroll
            for (int kt = 0; kt < 4; ++kt) ldm_x4(qh[kt], base + kt * 32);
        }

        if (t * AKT <= row_max) {
            const uint32_t kbuf = sb + ASM_KV + st_c * AKV_STAGE;
            const uint32_t vbuf = kbuf + 9216;

            float s[8][4];
            #pragma unroll
            for (int nt = 0; nt < 8; ++nt)
                #pragma unroll
                for (int f = 0; f < 4; ++f) s[nt][f] = 0.f;

            #pragma unroll
            for (int kt = 0; kt < 4; ++kt) {
                uint32_t kh[8][2];
                uint32_t kaddr = kbuf + krow * APITCH + kcb + kt * 32;
                #pragma unroll
                for (int p = 0; p < 4; ++p) {
                    uint32_t t4[4];
                    ldm_x4(t4, kaddr + p * 16 * APITCH);
                    kh[2 * p][0] = t4[0]; kh[2 * p][1] = t4[1];
                    kh[2 * p + 1][0] = t4[2]; kh[2 * p + 1][1] = t4[3];
                }
                #pragma unroll
                for (int nt = 0; nt < 8; ++nt)
                    mma_f16(s[nt], qh[kt], kh[nt]);
            }

            if (t >= ntiles - 2) {
                int r0 = q0 + w * 16 + (lane >> 2);
                int r1 = r0 + 8;
                #pragma unroll
                for (int nt = 0; nt < 8; ++nt) {
                    int c0 = t * AKT + nt * 8 + (lane & 3) * 2;
                    if (c0     > r0) s[nt][0] = -1e30f;
                    if (c0 + 1 > r0) s[nt][1] = -1e30f;
                    if (c0     > r1) s[nt][2] = -1e30f;
                    if (c0 + 1 > r1) s[nt][3] = -1e30f;
                }
            }

            float mx0 = -1e30f, mx1 = -1e30f;
            #pragma unroll
            for (int nt = 0; nt < 8; ++nt) {
                mx0 = fmaxf(mx0, fmaxf(s[nt][0], s[nt][1]));
                mx1 = fmaxf(mx1, fmaxf(s[nt][2], s[nt][3]));
            }
            #pragma unroll
            for (int ofs = 1; ofs <= 2; ofs <<= 1) {
                mx0 = fmaxf(mx0, __shfl_xor_sync(0xffffffffu, mx0, ofs));
                mx1 = fmaxf(mx1, __shfl_xor_sync(0xffffffffu, mx1, ofs));
            }
            float mn0 = fmaxf(m0, mx0), mn1 = fmaxf(m1, mx1);
            float cr0 = exp2f(m0 - mn0), cr1 = exp2f(m1 - mn1);
            float ps0 = 0.f, ps1 = 0.f;
            #pragma unroll
            for (int nt = 0; nt < 8; ++nt) {
                s[nt][0] = exp2f(s[nt][0] - mn0);
                s[nt][1] = exp2f(s[nt][1] - mn0);
                s[nt][2] = exp2f(s[nt][2] - mn1);
                s[nt][3] = exp2f(s[nt][3] - mn1);
                ps0 += s[nt][0] + s[nt][1];
                ps1 += s[nt][2] + s[nt][3];
            }
            #pragma unroll
            for (int ofs = 1; ofs <= 2; ofs <<= 1) {
                ps0 += __shfl_xor_sync(0xffffffffu, ps0, ofs);
                ps1 += __shfl_xor_sync(0xffffffffu, ps1, ofs);
            }
            l0 = l0 * cr0 + ps0;
            l1 = l1 * cr1 + ps1;
            m0 = mn0; m1 = mn1;
            #pragma unroll
            for (int nt = 0; nt < 8; ++nt) {
                o[nt][0] *= cr0; o[nt][1] *= cr0;
                o[nt][2] *= cr1; o[nt][3] *= cr1;
            }

            uint32_t ph[4][4];
            #pragma unroll
            for (int t2 = 0; t2 < 4; ++t2) {
                ph[t2][0] = pack_h2(__float2half(s[2*t2][0]),   __float2half(s[2*t2][1]));
                ph[t2][1] = pack_h2(__float2half(s[2*t2][2]),   __float2half(s[2*t2][3]));
                ph[t2][2] = pack_h2(__float2half(s[2*t2+1][0]), __float2half(s[2*t2+1][1]));
                ph[t2][3] = pack_h2(__float2half(s[2*t2+1][2]), __float2half(s[2*t2+1][3]));
            }

            #pragma unroll
            for (int kt2 = 0; kt2 < 4; ++kt2) {
                uint32_t vh[8][2];
                uint32_t vaddr = vbuf + (uint32_t)(kt2 * 16 + (lane & 15)) * APITCH + ((lane >> 4) << 4);
                #pragma unroll
                for (int p = 0; p < 4; ++p) {
                    uint32_t t4[4];
                    ldm_x4t(t4, vaddr + p * 32);
                    vh[2 * p][0] = t4[0]; vh[2 * p][1] = t4[1];
                    vh[2 * p + 1][0] = t4[2]; vh[2 * p + 1][1] = t4[3];
                }
                #pragma unroll
                for (int nt = 0; nt < 8; ++nt)
                    mma_f16(o[nt], ph[kt2], vh[nt]);
            }
        }
        st_c = (st_c == AKV_NS - 1) ? 0 : st_c + 1;
        st_i = (st_i == AKV_NS - 1) ? 0 : st_i + 1;
    }

    float i0 = 1.0f / l0, i1 = 1.0f / l1;
    size_t gr0 = tok0 + q0 + w * 16 + (lane >> 2);
    size_t gr1 = gr0 + 8;
    #pragma unroll
    for (int nt = 0; nt < 8; ++nt) {
        int col = hcol + nt * 8 + (lane & 3) * 2;
        *(uint32_t*)(ctx + gr0 * D_MOD + col) =
            pack_h2(__float2half(o[nt][0] * i0), __float2half(o[nt][1] * i0));
        *(uint32_t*)(ctx + gr1 * D_MOD + col) =
            pack_h2(__float2half(o[nt][2] * i1), __float2half(o[nt][3] * i1));
    }
}

// ---------------- confidence head (two-stage pooling) ----------------
__global__ void pool1_kernel(const float* __restrict__ xo, float* __restrict__ pp) {
    int blk = blockIdx.x;
    int b = blk >> 5, chunk = blk & 31;
    int d0 = threadIdx.x * 4;
    const float* base = xo + ((size_t)b * S_LEN + chunk * 64) * D_MOD + d0;
    float4 acc = make_float4(0.f, 0.f, 0.f, 0.f);
    #pragma unroll 4
    for (int t = 0; t < 64; ++t) {
        float4 v = *(const float4*)(base + (size_t)t * D_MOD);
        acc.x += v.x; acc.y += v.y; acc.z += v.z; acc.w += v.w;
    }
    *(float4*)(pp + (size_t)blk * D_MOD + d0) = acc;
}

__global__ void pool2_kernel(const float* __restrict__ pp, float* __restrict__ pooled) {
    int idx = blockIdx.x * blockDim.x + threadIdx.x;
    int b = idx >> 10, d = idx & 1023;
    const float* p = pp + (size_t)(b * 32) * D_MOD + d;
    float s = 0.f;
    #pragma unroll
    for (int c = 0; c < 32; ++c) s += p[(size_t)c * D_MOD];
    pooled[idx] = s * (1.0f / S_LEN);
}

__global__ void conf_kernel(const float* __restrict__ pooled, const float* __restrict__ cw,
                            const float* __restrict__ cb, float* __restrict__ out) {
    __shared__ float sred[8];
    float acc[B_SZ] = {};
    for (int d = threadIdx.x; d < D_MOD; d += 256) {
        float w = cw[d];
        #pragma unroll
        for (int b = 0; b < B_SZ; ++b) acc[b] += pooled[b * D_MOD + d] * w;
    }
    float dots[B_SZ];
    #pragma unroll
    for (int b = 0; b < B_SZ; ++b) dots[b] = block_sum_256(acc[b], sred);
    if (threadIdx.x == 0) {
        float s = 0.f;
        #pragma unroll
        for (int b = 0; b < B_SZ; ++b) s += 1.0f / (1.0f + __expf(-(dots[b] + cb[0])));
        out[0] = s * (1.0f / B_SZ);
    }
}

// ---------------- host launch ----------------
template <typename T>
static T* sym(const void* s) {
    void* p = nullptr;
    cudaGetSymbolAddress(&p, s);
    return (T*)p;
}

extern "C" void kernel_launch(void* const* d_in, const int* in_sizes, int n_in,
                              void* d_out, int out_size) {
    const float* x      = (const float*)d_in[0];
    const float* Wq     = (const float*)d_in[1];
    const float* Wk     = (const float*)d_in[2];
    const float* Wv     = (const float*)d_in[3];
    const float* Wo     = (const float*)d_in[4];
    const float* ln1_w  = (const float*)d_in[5];
    const float* ln1_b  = (const float*)d_in[6];
    const float* W1     = (const float*)d_in[7];
    const float* b1     = (const float*)d_in[8];
    const float* W2     = (const float*)d_in[9];
    const float* b2     = (const float*)d_in[10];
    const float* ln2_w  = (const float*)d_in[11];
    const float* ln2_b  = (const float*)d_in[12];
    const float* conf_w = (const float*)d_in[13];
    const float* conf_b = (const float*)d_in[14];
    float* out = (float*)d_out;

    __half* h    = sym<__half>(g_h);
    __half* qkv  = sym<__half>(g_qkv);
    __half* ctx  = sym<__half>(g_ctx);
    float*  x1   = sym<float>(g_x1);
    __half* mid  = sym<__half>(g_mid);
    float*  pl   = sym<float>(g_pool);
    float*  pp   = sym<float>(g_pp);
    __half* wqkv = sym<__half>(g_wqkv);
    __half* wo   = sym<__half>(g_wo);
    __half* w1   = sym<__half>(g_w1);
    __half* w2   = sym<__half>(g_w2);

    cudaFuncSetAttribute(hmma_gemm<false, false>, cudaFuncAttributeMaxDynamicSharedMemorySize, SM_TOT);
    cudaFuncSetAttribute(hmma_gemm<false, true >, cudaFuncAttributeMaxDynamicSharedMemorySize, SM_TOT);
    cudaFuncSetAttribute(hmma_gemm<true , true >, cudaFuncAttributeMaxDynamicSharedMemorySize, SM_TOT);
    cudaFuncSetAttribute(attn_mma, cudaFuncAttributeMaxDynamicSharedMemorySize, ASM_TOT);

    // ---- weight conversion (single launch) ----
    {
        int U = D_MOD * D_MOD / 4;
        conv_all<<<(12 * U) / 256, 256>>>(Wq, Wk, Wv, Wo, W1, W2, wqkv, wo, w1, w2);
    }

    const float QSCALE = 0.125f * 1.44269504f;   // log2(e)/sqrt(HD)

    // LN1 -> fp16 h
    ln_kernel<<<ROWS, 256>>>(x, ln1_w, ln1_b, h);
    // fused QKV projection -> fp16 (Q columns pre-scaled)
    dim3 gQKV(QKV_N / TCBN, ROWS / TCBM);   // (24, 64)
    hmma_gemm<false, true><<<gQKV, 256, SM_TOT>>>(h, wqkv,
        nullptr, nullptr, nullptr, qkv, ROWS, QKV_N, D_MOD, D_MOD, QSCALE);
    // causal attention -> fp16 ctx
    dim3 gA(S_LEN / AQ, B_SZ * N_HEAD);     // (16, 64)
    attn_mma<<<gA, 256, ASM_TOT>>>(qkv, ctx);
    // out-proj + residual -> fp32 x1
    dim3 gD(D_MOD / TCBN, ROWS / TCBM);     // (8, 64)
    hmma_gemm<false, false><<<gD, 256, SM_TOT>>>(ctx, wo,
        nullptr, x, x1, nullptr, ROWS, D_MOD, D_MOD, 0, 1.0f);
    // LN2 -> fp16 h
    ln_kernel<<<ROWS, 256>>>(x1, ln2_w, ln2_b, h);
    // FFN1 -> fp16 mid (relu)
    dim3 gF(F_DIM / TCBN, ROWS / TCBM);     // (32, 64)
    hmma_gemm<true, true><<<gF, 256, SM_TOT>>>(h, w1,
        b1, nullptr, nullptr, mid, ROWS, F_DIM, D_MOD, 0, 1.0f);
    // FFN2 -> out (+b2 + x1)
    hmma_gemm<false, false><<<gD, 256, SM_TOT>>>(mid, w2,
        b2, x1, out, nullptr, ROWS, D_MOD, F_DIM, 0, 1.0f);
    // confidence head
    pool1_kernel<<<B_SZ * 32, 256>>>(out, pp);
    pool2_kernel<<<16, 256>>>(pp, pl);
    conf_kernel<<<1, 256>>>(pl, conf_w, conf_b, out + (out_size - 1));
}

// round 16
// speedup vs baseline: 1.5591x; 1.5591x over previous
#include <cuda_runtime.h>
#include <cuda_fp16.h>
#include <cstdint>

// Problem constants
#define B_SZ   4
#define S_LEN  2048
#define D_MOD  1024
#define F_DIM  4096
#define N_HEAD 16
#define HD     64
#define ROWS   (B_SZ * S_LEN)        // 8192
#define QKV_N  (3 * D_MOD)           // 3072
#define LN_EPS 1e-5f

// ---------------- scratch (device globals; no allocation) ----------------
__device__ __half g_h  [ROWS * D_MOD];
__device__ __half g_qkv[ROWS * QKV_N];
__device__ __half g_ctx[ROWS * D_MOD];
__device__ float  g_x1 [ROWS * D_MOD];
__device__ __half g_mid[ROWS * F_DIM];
__device__ float  g_pool[B_SZ * D_MOD];
__device__ float  g_pp [B_SZ * 32 * D_MOD];
__device__ __half g_wqkv[D_MOD * QKV_N];
__device__ __half g_wo [D_MOD * D_MOD];
__device__ __half g_w1 [D_MOD * F_DIM];
__device__ __half g_w2 [F_DIM * D_MOD];

// ======================= helpers =======================
__device__ __forceinline__ uint32_t smem_u32(const void* p) {
    uint32_t a;
    asm("{ .reg .u64 t; cvta.to.shared.u64 t, %1; cvt.u32.u64 %0, t; }" : "=r"(a) : "l"(p));
    return a;
}
__device__ __forceinline__ void ldm_x4(uint32_t* r, uint32_t addr) {
    asm volatile("ldmatrix.sync.aligned.m8n8.x4.shared.b16 {%0,%1,%2,%3}, [%4];"
        : "=r"(r[0]), "=r"(r[1]), "=r"(r[2]), "=r"(r[3]) : "r"(addr));
}
__device__ __forceinline__ void ldm_x4t(uint32_t* r, uint32_t addr) {
    asm volatile("ldmatrix.sync.aligned.m8n8.x4.trans.shared.b16 {%0,%1,%2,%3}, [%4];"
        : "=r"(r[0]), "=r"(r[1]), "=r"(r[2]), "=r"(r[3]) : "r"(addr));
}
__device__ __forceinline__ void mma_f16(float* c, const uint32_t* a, const uint32_t* b) {
    asm volatile(
        "mma.sync.aligned.m16n8k16.row.col.f32.f16.f16.f32 "
        "{%0,%1,%2,%3}, {%4,%5,%6,%7}, {%8,%9}, {%0,%1,%2,%3};"
        : "+f"(c[0]), "+f"(c[1]), "+f"(c[2]), "+f"(c[3])
        : "r"(a[0]), "r"(a[1]), "r"(a[2]), "r"(a[3]), "r"(b[0]), "r"(b[1]));
}
__device__ __forceinline__ void cp16(uint32_t dst, const void* src) {
    asm volatile("cp.async.cg.shared.global [%0], [%1], 16;" :: "r"(dst), "l"(src));
}
__device__ __forceinline__ void cp_commit() { asm volatile("cp.async.commit_group;" ::: "memory"); }
template <int N>
__device__ __forceinline__ void cp_waitN() {
    asm volatile("cp.async.wait_group %0;" :: "n"(N) : "memory");
}
__device__ __forceinline__ uint32_t pack_h2(__half a, __half b) {
    __half2 v; v.x = a; v.y = b;
    return *reinterpret_cast<uint32_t*>(&v);
}
__device__ __forceinline__ float ex2(float x) {      // single MUFU.EX2
    float r;
    asm("ex2.approx.ftz.f32 %0, %1;" : "=f"(r) : "f"(x));
    return r;
}

// ======================= pipelined HMMA GEMM (fp16, 128x128, BK=32, 3-stage, 1 sync/chunk) =======================
#define TCBM 128
#define TCBN 128
#define TCBK 32
#define A_PITCH 80
#define B_PITCH 272
#define SM_A    0
#define SM_B    10240
#define SM_BUF  18944
#define N_STAGE 3
#define SM_TOT  (N_STAGE * SM_BUF)     // 56832

// qcols: SPLIT-output columns < qcols are scaled by qscale (Q pre-scaling for attention)
template <bool RELU, bool SPLIT>
__global__ __launch_bounds__(256, 2) void hmma_gemm(
    const __half* __restrict__ A, const __half* __restrict__ Bm,
    const float* __restrict__ bias, const float* __restrict__ resid,
    float* __restrict__ C, __half* __restrict__ Ch,
    int M, int N, int K, int qcols, float qscale)
{
    extern __shared__ char smem[];
    const uint32_t sb = smem_u32(smem);

    const int tid = threadIdx.x;
    const int wid = tid >> 5, lane = tid & 31;
    const int warp_m = wid & 1;
    const int warp_n = wid >> 1;
    const int m0 = blockIdx.y * TCBM, n0 = blockIdx.x * TCBN;

    const int aR0 = tid >> 1, aC0 = (tid & 1) << 1;
    const int bR0 = tid >> 3, bC0 = (tid & 7) << 1;

    float c[4][4][4];
    #pragma unroll
    for (int i = 0; i < 4; ++i)
        #pragma unroll
        for (int j = 0; j < 4; ++j)
            #pragma unroll
            for (int f = 0; f < 4; ++f) c[i][j][f] = 0.f;

    const uint32_t a_row = (uint32_t)(warp_m * 64 + (lane & 15));
    const uint32_t a_cb  = (uint32_t)((lane >> 4) << 4);
    const uint32_t b_row = (uint32_t)(lane & 15);
    const uint32_t b_cb  = (uint32_t)(warp_n * 64 + ((lane >> 4) << 4));

    const int NC = K / TCBK;

    auto issue = [&](int ch, int st) {
        const uint32_t bb = sb + st * SM_BUF;
        const int k0 = ch * TCBK;
        #pragma unroll
        for (int i = 0; i < 2; ++i) {
            int ck = aC0 + i;
            cp16(bb + SM_A + aR0 * A_PITCH + ck * 16,
                 A + (size_t)(m0 + aR0) * K + k0 + ck * 8);
        }
        #pragma unroll
        for (int i = 0; i < 2; ++i) {
            int ck = bC0 + i;
            cp16(bb + SM_B + bR0 * B_PITCH + ck * 16,
                 Bm + (size_t)(k0 + bR0) * N + n0 + ck * 8);
        }
        cp_commit();
    };

    issue(0, 0); issue(1, 1);

    int st_c = 0, st_i = 2;
    for (int ch = 0; ch < NC; ++ch) {
        cp_waitN<1>();
        __syncthreads();
        if (ch + 2 < NC) issue(ch + 2, st_i);
        else             cp_commit();

        const uint32_t bb = sb + st_c * SM_BUF;
        #pragma unroll
        for (int ks = 0; ks < 2; ++ks) {
            uint32_t bh[4][2];
            uint32_t b_addr = bb + SM_B + (b_row + ks * 16) * B_PITCH + b_cb;
            #pragma unroll
            for (int nt2 = 0; nt2 < 2; ++nt2) {
                uint32_t t4[4];
                ldm_x4t(t4, b_addr + nt2 * 32);
                bh[nt2 * 2][0] = t4[0]; bh[nt2 * 2][1] = t4[1];
                bh[nt2 * 2 + 1][0] = t4[2]; bh[nt2 * 2 + 1][1] = t4[3];
            }
            uint32_t a_addr = bb + SM_A + a_row * A_PITCH + a_cb + ks * 32;
            #pragma unroll
            for (int mt = 0; mt < 4; ++mt) {
                uint32_t ah[4];
                ldm_x4(ah, a_addr + mt * 16 * A_PITCH);
                #pragma unroll
                for (int nt = 0; nt < 4; ++nt)
                    mma_f16(c[mt][nt], ah, bh[nt]);
            }
        }
        st_c = (st_c == N_STAGE - 1) ? 0 : st_c + 1;
        st_i = (st_i == N_STAGE - 1) ? 0 : st_i + 1;
    }

    const int er = lane >> 2, ec = (lane & 3) * 2;
    #pragma unroll
    for (int mt = 0; mt < 4; ++mt) {
        #pragma unroll
        for (int nt = 0; nt < 4; ++nt) {
            int gr = m0 + warp_m * 64 + mt * 16 + er;
            int gc = n0 + warp_n * 32 + nt * 8 + ec;
            #pragma unroll
            for (int half = 0; half < 2; ++half) {
                int row = gr + half * 8;
                float v0 = c[mt][nt][half * 2 + 0];
                float v1 = c[mt][nt][half * 2 + 1];
                if (bias) { v0 += bias[gc]; v1 += bias[gc + 1]; }
                if (resid) {
                    float2 r2 = *(const float2*)(resid + (size_t)row * N + gc);
                    v0 += r2.x; v1 += r2.y;
                }
                if (RELU) { v0 = fmaxf(v0, 0.f); v1 = fmaxf(v1, 0.f); }
                if (SPLIT) {
                    if (gc < qcols) { v0 *= qscale; v1 *= qscale; }
                    *(uint32_t*)(Ch + (size_t)row * N + gc) =
                        pack_h2(__float2half(v0), __float2half(v1));
                } else {
                    *(float2*)(C + (size_t)row * N + gc) = make_float2(v0, v1);
                }
            }
        }
    }
}

// ---------------- fused weight convert: all 6 matrices in one launch ----------------
__global__ void conv_all(const float* __restrict__ Wq, const float* __restrict__ Wk,
                         const float* __restrict__ Wv, const float* __restrict__ Wo,
                         const float* __restrict__ W1, const float* __restrict__ W2,
                         __half* __restrict__ wqkv, __half* __restrict__ wo,
                         __half* __restrict__ w1, __half* __restrict__ w2) {
    const int U = D_MOD * D_MOD / 4;
    int idx = blockIdx.x * blockDim.x + threadIdx.x;
    const float* src; __half* dst;
    int cols, dstride, coff;
    if (idx < U)          { src = Wq; dst = wqkv; cols = D_MOD; dstride = QKV_N; coff = 0; }
    else if (idx < 2 * U) { src = Wk; dst = wqkv; cols = D_MOD; dstride = QKV_N; coff = D_MOD;   idx -= U; }
    else if (idx < 3 * U) { src = Wv; dst = wqkv; cols = D_MOD; dstride = QKV_N; coff = 2*D_MOD; idx -= 2*U; }
    else if (idx < 4 * U) { src = Wo; dst = wo;   cols = D_MOD; dstride = D_MOD; coff = 0; idx -= 3*U; }
    else if (idx < 8 * U) { src = W1; dst = w1;   cols = F_DIM; dstride = F_DIM; coff = 0; idx -= 4*U; }
    else                  { src = W2; dst = w2;   cols = D_MOD; dstride = D_MOD; coff = 0; idx -= 8*U; }
    float4 v = *(const float4*)(src + (size_t)idx * 4);
    int e = idx * 4;
    int r = e / cols, cc = e % cols;
    size_t d = (size_t)r * dstride + coff + cc;
    *(uint2*)(dst + d) = make_uint2(pack_h2(__float2half(v.x), __float2half(v.y)),
                                    pack_h2(__float2half(v.z), __float2half(v.w)));
}

// ---------------- block reduction helper ----------------
__device__ __forceinline__ float block_sum_256(float v, float* sred) {
    int lane = threadIdx.x & 31, w = threadIdx.x >> 5;
    #pragma unroll
    for (int o = 16; o; o >>= 1) v += __shfl_xor_sync(0xffffffffu, v, o);
    if (lane == 0) sred[w] = v;
    __syncthreads();
    float r = (threadIdx.x < 8) ? sred[threadIdx.x] : 0.0f;
    if (w == 0) {
        #pragma unroll
        for (int o = 4; o; o >>= 1) r += __shfl_xor_sync(0x000000ffu, r, o);
        if (lane == 0) sred[0] = r;
    }
    __syncthreads();
    float out = sred[0];
    __syncthreads();
    return out;
}

// ---------------- LayerNorm -> fp16 (vectorized) ----------------
__global__ void ln_kernel(const float* __restrict__ x, const float* __restrict__ w,
                          const float* __restrict__ b, __half* __restrict__ oh) {
    __shared__ float sred[8];
    size_t row = blockIdx.x;
    int t = threadIdx.x;
    float4 v = *(const float4*)(x + row * D_MOD + t * 4);
    float s = v.x + v.y + v.z + v.w;
    float mu = block_sum_256(s, sred) * (1.0f / D_MOD);
    float dx = v.x - mu, dy = v.y - mu, dz = v.z - mu, dw = v.w - mu;
    float d2 = dx * dx + dy * dy + dz * dz + dw * dw;
    float var = block_sum_256(d2, sred) * (1.0f / D_MOD);
    float inv = rsqrtf(var + LN_EPS);
    float4 wv = *(const float4*)(w + t * 4);
    float4 bv = *(const float4*)(b + t * 4);
    __half h0 = __float2half(dx * inv * wv.x + bv.x);
    __half h1 = __float2half(dy * inv * wv.y + bv.y);
    __half h2 = __float2half(dz * inv * wv.z + bv.z);
    __half h3 = __float2half(dw * inv * wv.w + bv.w);
    *(uint2*)(oh + row * D_MOD + t * 4) = make_uint2(pack_h2(h0, h1), pack_h2(h2, h3));
}

// ======================= MMA flash attention (causal, fp16, BQ=128, 3-stage KV) =======================
// Q pre-scaled by log2(e)/sqrt(HD); softmax via ex2.approx (exp2 domain).
#define AQ 128
#define AKT 64
#define APITCH 144
#define ASM_Q 0
#define ASM_KV 18432
#define AKV_STAGE 18432
#define AKV_NS 3
#define ASM_TOT (ASM_KV + AKV_NS * AKV_STAGE)    // 73728

__global__ __launch_bounds__(256, 2) void attn_mma(
    const __half* __restrict__ qkv, __half* __restrict__ ctx)
{
    extern __shared__ char sm[];
    const uint32_t sb = smem_u32(sm);
    const int qb = blockIdx.x;
    const int bh = blockIdx.y;
    const int b = bh >> 4, h = bh & 15;
    const int tid = threadIdx.x, w = tid >> 5, lane = tid & 31;
    const size_t tok0 = (size_t)b * S_LEN;
    const int q0 = qb * AQ;
    const int hcol = h * HD;

    auto issue_kv = [&](int t, int st) {
        const uint32_t kb = sb + ASM_KV + st * AKV_STAGE;
        #pragma unroll
        for (int i = 0; i < 2; ++i) {
            int idx = i * 256 + tid;
            int r = idx >> 3, ck = idx & 7;
            size_t gk = (tok0 + t * AKT + r) * QKV_N + hcol + D_MOD + ck * 8;
            uint32_t off = (uint32_t)(r * APITCH + ck * 16);
            cp16(kb + off, qkv + gk);
            cp16(kb + 9216 + off, qkv + gk + D_MOD);
        }
        cp_commit();
    };

    #pragma unroll
    for (int i = 0; i < 4; ++i) {
        int idx = i * 256 + tid;
        int r = idx >> 3, ck = idx & 7;
        cp16(sb + ASM_Q + r * APITCH + ck * 16,
             qkv + (tok0 + q0 + r) * QKV_N + hcol + ck * 8);
    }
    issue_kv(0, 0);
    issue_kv(1, 1);

    uint32_t qh[4][4];
    float o[8][4];
    #pragma unroll
    for (int nt = 0; nt < 8; ++nt)
        #pragma unroll
        for (int f = 0; f < 4; ++f) o[nt][f] = 0.f;
    float m0 = -1e30f, m1 = -1e30f, l0 = 0.f, l1 = 0.f;

    const uint32_t krow = (uint32_t)((lane & 7) + ((lane >> 4) << 3));
    const uint32_t kcb  = (uint32_t)(((lane >> 3) & 1) << 4);
    const int row_max = q0 + w * 16 + 15;

    const int ntiles = 2 * qb + 2;
    int st_c = 0, st_i = 2;
    for (int t = 0; t < ntiles; ++t) {
        cp_waitN<1>();
        __syncthreads();
        if (t + 2 < ntiles) issue_kv(t + 2, st_i);
        else                cp_commit();

        if (t == 0) {
            uint32_t base = sb + ASM_Q + (uint32_t)(w * 16 + (lane & 15)) * APITCH + ((lane >> 4) << 4);
            #pragma unroll
            for (int kt = 0; kt < 4; ++kt) ldm_x4(qh[kt], base + kt * 32);
        }

        if (t * AKT <= row_max) {
            const uint32_t kbuf = sb + ASM_KV + st_c * AKV_STAGE;
            const uint32_t vbuf = kbuf + 9216;

            float s[8][4];
            #pragma unroll
            for (int nt = 0; nt < 8; ++nt)
                #pragma unroll
                for (int f = 0; f < 4; ++f) s[nt][f] = 0.f;

            #pragma unroll
            for (int kt = 0; kt < 4; ++kt) {
                uint32_t kh[8][2];
                uint32_t kaddr = kbuf + krow * APITCH + kcb + kt * 32;
                #pragma unroll
                for (int p = 0; p < 4; ++p) {
                    uint32_t t4[4];
                    ldm_x4(t4, kaddr + p * 16 * APITCH);
                    kh[2 * p][0] = t4[0]; kh[2 * p][1] = t4[1];
                    kh[2 * p + 1][0] = t4[2]; kh[2 * p + 1][1] = t4[3];
                }
                #pragma unroll
                for (int nt = 0; nt < 8; ++nt)
                    mma_f16(s[nt], qh[kt], kh[nt]);
            }

            if (t >= ntiles - 2) {
                int r0 = q0 + w * 16 + (lane >> 2);
                int r1 = r0 + 8;
                #pragma unroll
                for (int nt = 0; nt < 8; ++nt) {
                    int c0 = t * AKT + nt * 8 + (lane & 3) * 2;
                    if (c0     > r0) s[nt][0] = -1e30f;
                    if (c0 + 1 > r0) s[nt][1] = -1e30f;
                    if (c0     > r1) s[nt][2] = -1e30f;
                    if (c0 + 1 > r1) s[nt][3] = -1e30f;
                }
            }

            float mx0 = -1e30f, mx1 = -1e30f;
            #pragma unroll
            for (int nt = 0; nt < 8; ++nt) {
                mx0 = fmaxf(mx0, fmaxf(s[nt][0], s[nt][1]));
                mx1 = fmaxf(mx1, fmaxf(s[nt][2], s[nt][3]));
            }
            #pragma unroll
            for (int ofs = 1; ofs <= 2; ofs <<= 1) {
                mx0 = fmaxf(mx0, __shfl_xor_sync(0xffffffffu, mx0, ofs));
                mx1 = fmaxf(mx1, __shfl_xor_sync(0xffffffffu, mx1, ofs));
            }
            float mn0 = fmaxf(m0, mx0), mn1 = fmaxf(m1, mx1);
            float cr0 = ex2(m0 - mn0), cr1 = ex2(m1 - mn1);
            float ps0 = 0.f, ps1 = 0.f;
            #pragma unroll
            for (int nt = 0; nt < 8; ++nt) {
                s[nt][0] = ex2(s[nt][0] - mn0);
                s[nt][1] = ex2(s[nt][1] - mn0);
                s[nt][2] = ex2(s[nt][2] - mn1);
                s[nt][3] = ex2(s[nt][3] - mn1);
                ps0 += s[nt][0] + s[nt][1];
                ps1 += s[nt][2] + s[nt][3];
            }
            #pragma unroll
            for (int ofs = 1; ofs <= 2; ofs <<= 1) {
                ps0 += __shfl_xor_sync(0xffffffffu, ps0, ofs);
                ps1 += __shfl_xor_sync(0xffffffffu, ps1, ofs);
            }
            l0 = l0 * cr0 + ps0;
            l1 = l1 * cr1 + ps1;
            m0 = mn0; m1 = mn1;
            #pragma unroll
            for (int nt = 0; nt < 8; ++nt) {
                o[nt][0] *= cr0; o[nt][1] *= cr0;
                o[nt][2] *= cr1; o[nt][3] *= cr1;
            }

            uint32_t ph[4][4];
            #pragma unroll
            for (int t2 = 0; t2 < 4; ++t2) {
                ph[t2][0] = pack_h2(__float2half(s[2*t2][0]),   __float2half(s[2*t2][1]));
                ph[t2][1] = pack_h2(__float2half(s[2*t2][2]),   __float2half(s[2*t2][3]));
                ph[t2][2] = pack_h2(__float2half(s[2*t2+1][0]), __float2half(s[2*t2+1][1]));
                ph[t2][3] = pack_h2(__float2half(s[2*t2+1][2]), __float2half(s[2*t2+1][3]));
            }

            #pragma unroll
            for (int kt2 = 0; kt2 < 4; ++kt2) {
                uint32_t vh[8][2];
                uint32_t vaddr = vbuf + (uint32_t)(kt2 * 16 + (lane & 15)) * APITCH + ((lane >> 4) << 4);
                #pragma unroll
                for (int p = 0; p < 4; ++p) {
                    uint32_t t4[4];
                    ldm_x4t(t4, vaddr + p * 32);
                    vh[2 * p][0] = t4[0]; vh[2 * p][1] = t4[1];
                    vh[2 * p + 1][0] = t4[2]; vh[2 * p + 1][1] = t4[3];
                }
                #pragma unroll
                for (int nt = 0; nt < 8; ++nt)
                    mma_f16(o[nt], ph[kt2], vh[nt]);
            }
        }
        st_c = (st_c == AKV_NS - 1) ? 0 : st_c + 1;
        st_i = (st_i == AKV_NS - 1) ? 0 : st_i + 1;
    }

    float i0 = 1.0f / l0, i1 = 1.0f / l1;
    size_t gr0 = tok0 + q0 + w * 16 + (lane >> 2);
    size_t gr1 = gr0 + 8;
    #pragma unroll
    for (int nt = 0; nt < 8; ++nt) {
        int col = hcol + nt * 8 + (lane & 3) * 2;
        *(uint32_t*)(ctx + gr0 * D_MOD + col) =
            pack_h2(__float2half(o[nt][0] * i0), __float2half(o[nt][1] * i0));
        *(uint32_t*)(ctx + gr1 * D_MOD + col) =
            pack_h2(__float2half(o[nt][2] * i1), __float2half(o[nt][3] * i1));
    }
}

// ---------------- confidence head (two-stage pooling) ----------------
__global__ void pool1_kernel(const float* __restrict__ xo, float* __restrict__ pp) {
    int blk = blockIdx.x;
    int b = blk >> 5, chunk = blk & 31;
    int d0 = threadIdx.x * 4;
    const float* base = xo + ((size_t)b * S_LEN + chunk * 64) * D_MOD + d0;
    float4 acc = make_float4(0.f, 0.f, 0.f, 0.f);
    #pragma unroll 4
    for (int t = 0; t < 64; ++t) {
        float4 v = *(const float4*)(base + (size_t)t * D_MOD);
        acc.x += v.x; acc.y += v.y; acc.z += v.z; acc.w += v.w;
    }
    *(float4*)(pp + (size_t)blk * D_MOD + d0) = acc;
}

__global__ void pool2_kernel(const float* __restrict__ pp, float* __restrict__ pooled) {
    int idx = blockIdx.x * blockDim.x + threadIdx.x;
    int b = idx >> 10, d = idx & 1023;
    const float* p = pp + (size_t)(b * 32) * D_MOD + d;
    float s = 0.f;
    #pragma unroll
    for (int c = 0; c < 32; ++c) s += p[(size_t)c * D_MOD];
    pooled[idx] = s * (1.0f / S_LEN);
}

__global__ void conf_kernel(const float* __restrict__ pooled, const float* __restrict__ cw,
                            const float* __restrict__ cb, float* __restrict__ out) {
    __shared__ float sred[8];
    float acc[B_SZ] = {};
    for (int d = threadIdx.x; d < D_MOD; d += 256) {
        float w = cw[d];
        #pragma unroll
        for (int b = 0; b < B_SZ; ++b) acc[b] += pooled[b * D_MOD + d] * w;
    }
    float dots[B_SZ];
    #pragma unroll
    for (int b = 0; b < B_SZ; ++b) dots[b] = block_sum_256(acc[b], sred);
    if (threadIdx.x == 0) {
        float s = 0.f;
        #pragma unroll
        for (int b = 0; b < B_SZ; ++b) s += 1.0f / (1.0f + __expf(-(dots[b] + cb[0])));
        out[0] = s * (1.0f / B_SZ);
    }
}

// ---------------- host launch ----------------
template <typename T>
static T* sym(const void* s) {
    void* p = nullptr;
    cudaGetSymbolAddress(&p, s);
    return (T*)p;
}

extern "C" void kernel_launch(void* const* d_in, const int* in_sizes, int n_in,
                              void* d_out, int out_size) {
    const float* x      = (const float*)d_in[0];
    const float* Wq     = (const float*)d_in[1];
    const float* Wk     = (const float*)d_in[2];
    const float* Wv     = (const float*)d_in[3];
    const float* Wo     = (const float*)d_in[4];
    const float* ln1_w  = (const float*)d_in[5];
    const float* ln1_b  = (const float*)d_in[6];
    const float* W1     = (const float*)d_in[7];
    const float* b1     = (const float*)d_in[8];
    const float* W2     = (const float*)d_in[9];
    const float* b2     = (const float*)d_in[10];
    const float* ln2_w  = (const float*)d_in[11];
    const float* ln2_b  = (const float*)d_in[12];
    const float* conf_w = (const float*)d_in[13];
    const float* conf_b = (const float*)d_in[14];
    float* out = (float*)d_out;

    __half* h    = sym<__half>(g_h);
    __half* qkv  = sym<__half>(g_qkv);
    __half* ctx  = sym<__half>(g_ctx);
    float*  x1   = sym<float>(g_x1);
    __half* mid  = sym<__half>(g_mid);
    float*  pl   = sym<float>(g_pool);
    float*  pp   = sym<float>(g_pp);
    __half* wqkv = sym<__half>(g_wqkv);
    __half* wo   = sym<__half>(g_wo);
    __half* w1   = sym<__half>(g_w1);
    __half* w2   = sym<__half>(g_w2);

    cudaFuncSetAttribute(hmma_gemm<false, false>, cudaFuncAttributeMaxDynamicSharedMemorySize, SM_TOT);
    cudaFuncSetAttribute(hmma_gemm<false, true >, cudaFuncAttributeMaxDynamicSharedMemorySize, SM_TOT);
    cudaFuncSetAttribute(hmma_gemm<true , true >, cudaFuncAttributeMaxDynamicSharedMemorySize, SM_TOT);
    cudaFuncSetAttribute(attn_mma, cudaFuncAttributeMaxDynamicSharedMemorySize, ASM_TOT);

    // ---- weight conversion (single launch) ----
    {
        int U = D_MOD * D_MOD / 4;
        conv_all<<<(12 * U) / 256, 256>>>(Wq, Wk, Wv, Wo, W1, W2, wqkv, wo, w1, w2);
    }

    const float QSCALE = 0.125f * 1.44269504f;   // log2(e)/sqrt(HD)

    // LN1 -> fp16 h
    ln_kernel<<<ROWS, 256>>>(x, ln1_w, ln1_b, h);
    // fused QKV projection -> fp16 (Q columns pre-scaled)
    dim3 gQKV(QKV_N / TCBN, ROWS / TCBM);   // (24, 64)
    hmma_gemm<false, true><<<gQKV, 256, SM_TOT>>>(h, wqkv,
        nullptr, nullptr, nullptr, qkv, ROWS, QKV_N, D_MOD, D_MOD, QSCALE);
    // causal attention -> fp16 ctx
    dim3 gA(S_LEN / AQ, B_SZ * N_HEAD);     // (16, 64)
    attn_mma<<<gA, 256, ASM_TOT>>>(qkv, ctx);
    // out-proj + residual -> fp32 x1
    dim3 gD(D_MOD / TCBN, ROWS / TCBM);     // (8, 64)
    hmma_gemm<false, false><<<gD, 256, SM_TOT>>>(ctx, wo,
        nullptr, x, x1, nullptr, ROWS, D_MOD, D_MOD, 0, 1.0f);
    // LN2 -> fp16 h
    ln_kernel<<<ROWS, 256>>>(x1, ln2_w, ln2_b, h);
    // FFN1 -> fp16 mid (relu)
    dim3 gF(F_DIM / TCBN, ROWS / TCBM);     // (32, 64)
    hmma_gemm<true, true><<<gF, 256, SM_TOT>>>(h, w1,
        b1, nullptr, nullptr, mid, ROWS, F_DIM, D_MOD, 0, 1.0f);
    // FFN2 -> out (+b2 + x1)
    hmma_gemm<false, false><<<gD, 256, SM_TOT>>>(mid, w2,
        b2, x1, out, nullptr, ROWS, D_MOD, F_DIM, 0, 1.0f);
    // confidence head
    pool1_kernel<<<B_SZ * 32, 256>>>(out, pp);
    pool2_kernel<<<16, 256>>>(pp, pl);
    conf_kernel<<<1, 256>>>(pl, conf_w, conf_b, out + (out_size - 1));
}